// round 2
// baseline (speedup 1.0000x reference)
#include <cuda_runtime.h>
#include <math.h>

#define OW 128
#define OH 32
#define RAD 15
#define LW (OW + 2*RAD)   // 158
#define LH (OH + 2*RAD)   // 62
#define SW 160            // padded shared row stride (floats)
#define IMH 1024
#define IMW 1024
#define NB 8
#define SMEM_BYTES ((LH + OH + OH) * SW * 4)   // 80640

__device__ float d_g31[31];
__device__ float d_g7[7];
__device__ float d_amt[2];

__global__ void init_weights_k(const float* __restrict__ clar,
                               const float* __restrict__ tex) {
    int t = threadIdx.x;  // 32 threads
    // 31-tap gaussian, sigma = 8
    float w31 = 0.f;
    if (t < 31) {
        float d = (float)(t - 15);
        w31 = expf(-d * d / (2.f * 8.f * 8.f));
    }
    float s = w31;
    #pragma unroll
    for (int o = 16; o; o >>= 1) s += __shfl_xor_sync(0xffffffffu, s, o);
    if (t < 31) d_g31[t] = w31 / s;

    // 7-tap gaussian, sigma = 1.5
    float w7 = 0.f;
    if (t < 7) {
        float d = (float)(t - 3);
        w7 = expf(-d * d / (2.f * 1.5f * 1.5f));
    }
    float s7 = w7;
    #pragma unroll
    for (int o = 16; o; o >>= 1) s7 += __shfl_xor_sync(0xffffffffu, s7, o);
    if (t < 7) d_g7[t] = w7 / s7;

    if (t == 0) {
        d_amt[0] = tanhf(*clar) * 0.5f;
        d_amt[1] = tanhf(*tex) * 0.3f;
    }
}

__device__ __forceinline__ float clamp01(float v) {
    return fminf(fmaxf(v, 0.f), 1.f);
}

__global__ __launch_bounds__(256, 2)
void clarity_texture_kernel(const float* __restrict__ x, float* __restrict__ out) {
    extern __shared__ float smem[];
    float* sLuma = smem;                 // LH x SW
    float* sV31  = smem + LH * SW;       // OH x SW
    float* sV7   = sV31 + OH * SW;       // OH x SW

    const int tid = threadIdx.x;
    const int x0 = blockIdx.x * OW;
    const int y0 = blockIdx.y * OH;
    const int b  = blockIdx.z;

    // weights into registers (indices constant after full unroll)
    float rg31[31], rg7[7];
    #pragma unroll
    for (int k = 0; k < 31; k++) rg31[k] = d_g31[k];
    #pragma unroll
    for (int k = 0; k < 7; k++)  rg7[k]  = d_g7[k];
    const float ca = d_amt[0];
    const float ta = d_amt[1];

    const size_t plane = (size_t)IMH * IMW;
    const float* xb = x + (size_t)b * 3 * plane;
    float* ob = out + (size_t)b * 3 * plane;

    // ---- Phase 1: luma tile with halo (zero padding outside image) ----
    for (int i = tid; i < LH * LW; i += 256) {
        int row = i / LW, col = i % LW;
        int gy = y0 - RAD + row;
        int gx = x0 - RAD + col;
        float l = 0.f;
        if (gy >= 0 && gy < IMH && gx >= 0 && gx < IMW) {
            size_t idx = (size_t)gy * IMW + gx;
            l = 0.2126f * xb[idx]
              + 0.7152f * xb[idx + plane]
              + 0.0722f * xb[idx + 2 * plane];
        }
        sLuma[row * SW + col] = l;
    }
    __syncthreads();

    // ---- Phase 2: vertical 31-tap + 7-tap blurs, 4 output rows per thread ----
    for (int s = tid; s < LW * (OH / 4); s += 256) {
        int col = s % LW;
        int r0  = (s / LW) * 4;
        float a31[4] = {0.f, 0.f, 0.f, 0.f};
        float a7[4]  = {0.f, 0.f, 0.f, 0.f};
        #pragma unroll
        for (int k = 0; k < 34; k++) {
            float v = sLuma[(r0 + k) * SW + col];
            #pragma unroll
            for (int o = 0; o < 4; o++) {
                int j = k - o;
                if (j >= 0 && j <= 30) a31[o] += rg31[j] * v;
                int j7 = j - 12;
                if (j7 >= 0 && j7 <= 6) a7[o] += rg7[j7] * v;
            }
        }
        #pragma unroll
        for (int o = 0; o < 4; o++) {
            sV31[(r0 + o) * SW + col] = a31[o];
            sV7 [(r0 + o) * SW + col] = a7[o];
        }
    }
    __syncthreads();

    // ---- Phase 3: horizontal blurs + combine + clip, 4 output cols per thread ----
    for (int s = tid; s < OH * (OW / 4); s += 256) {
        int cstrip = s % (OW / 4);
        int r = s / (OW / 4);
        int c0 = cstrip * 4;

        float a31[4] = {0.f, 0.f, 0.f, 0.f};
        float a7[4]  = {0.f, 0.f, 0.f, 0.f};

        // 31-tap horizontal: window floats [c0, c0+33], loaded as 9 float4
        const float4* p31 = (const float4*)&sV31[r * SW + c0];
        #pragma unroll
        for (int chk = 0; chk < 9; chk++) {
            float4 v4 = p31[chk];
            float e[4] = {v4.x, v4.y, v4.z, v4.w};
            #pragma unroll
            for (int q = 0; q < 4; q++) {
                int m = chk * 4 + q;
                #pragma unroll
                for (int o = 0; o < 4; o++) {
                    int k = m - o;
                    if (k >= 0 && k <= 30) a31[o] += rg31[k] * e[q];
                }
            }
        }
        // 7-tap horizontal: window floats [c0+12, c0+21], loaded as 3 float4
        const float4* p7 = (const float4*)&sV7[r * SW + c0 + 12];
        #pragma unroll
        for (int chk = 0; chk < 3; chk++) {
            float4 v4 = p7[chk];
            float e[4] = {v4.x, v4.y, v4.z, v4.w};
            #pragma unroll
            for (int q = 0; q < 4; q++) {
                int m = chk * 4 + q;
                #pragma unroll
                for (int o = 0; o < 4; o++) {
                    int k = m - o;
                    if (k >= 0 && k <= 6) a7[o] += rg7[k] * e[q];
                }
            }
        }

        float ratio[4];
        #pragma unroll
        for (int o = 0; o < 4; o++) {
            float lum = sLuma[(r + RAD) * SW + (c0 + o + RAD)];
            float le  = lum + ca * (lum - a31[o]) + ta * (lum - a7[o]);
            ratio[o]  = (le + 1e-6f) / (lum + 1e-6f);
        }

        int gy = y0 + r;
        int gx = x0 + c0;
        size_t idx = (size_t)gy * IMW + gx;
        float4 xc0 = *(const float4*)&xb[idx];
        float4 xc1 = *(const float4*)&xb[idx + plane];
        float4 xc2 = *(const float4*)&xb[idx + 2 * plane];

        float4 o0, o1, o2;
        o0.x = clamp01(xc0.x * ratio[0]); o0.y = clamp01(xc0.y * ratio[1]);
        o0.z = clamp01(xc0.z * ratio[2]); o0.w = clamp01(xc0.w * ratio[3]);
        o1.x = clamp01(xc1.x * ratio[0]); o1.y = clamp01(xc1.y * ratio[1]);
        o1.z = clamp01(xc1.z * ratio[2]); o1.w = clamp01(xc1.w * ratio[3]);
        o2.x = clamp01(xc2.x * ratio[0]); o2.y = clamp01(xc2.y * ratio[1]);
        o2.z = clamp01(xc2.z * ratio[2]); o2.w = clamp01(xc2.w * ratio[3]);

        *(float4*)&ob[idx]             = o0;
        *(float4*)&ob[idx + plane]     = o1;
        *(float4*)&ob[idx + 2 * plane] = o2;
    }
}

extern "C" void kernel_launch(void* const* d_in, const int* in_sizes, int n_in,
                              void* d_out, int out_size) {
    const float* x    = (const float*)d_in[0];
    const float* clar = (const float*)d_in[1];
    const float* tex  = (const float*)d_in[2];
    float* out = (float*)d_out;

    cudaFuncSetAttribute(clarity_texture_kernel,
                         cudaFuncAttributeMaxDynamicSharedMemorySize, SMEM_BYTES);

    init_weights_k<<<1, 32>>>(clar, tex);

    dim3 grid(IMW / OW, IMH / OH, NB);
    clarity_texture_kernel<<<grid, 256, SMEM_BYTES>>>(x, out);
}

// round 7
// speedup vs baseline: 1.1846x; 1.1846x over previous
#include <cuda_runtime.h>
#include <math.h>

#define IMW 1024
#define IMH 1024
#define NB  8
#define OW  128
#define OH  32
#define LW  160          // luma tile cols: global x in [x0-16, x0+144)
#define LH  62           // luma tile rows: global y in [y0-15, y0+47)
#define SW  160          // shared row stride (floats)
#define SMEM_FLOATS (LH*SW + OH*SW)      // 9920 + 5120 = 15040
#define SMEM_BYTES  (SMEM_FLOATS * 4)    // 60160 -> 3 CTAs/SM

// 31-tap gaussian (sigma=8), normalized, k=0..30 (center 15)
__device__ constexpr float G31[31] = {
    0.0090750f, 0.0113825f, 0.0140557f, 0.0170873f, 0.0204508f, 0.0240970f,
    0.0279530f, 0.0319233f, 0.0358923f, 0.0397292f, 0.0432944f, 0.0464481f,
    0.0490592f, 0.0510133f, 0.0522230f, 0.0526326f, 0.0522230f, 0.0510133f,
    0.0490592f, 0.0464481f, 0.0432944f, 0.0397292f, 0.0358923f, 0.0319233f,
    0.0279530f, 0.0240970f, 0.0204508f, 0.0170873f, 0.0140557f, 0.0113825f,
    0.0090750f
};
// 7-tap gaussian (sigma=1.5), normalized
__device__ constexpr float G7[7] = {
    0.0366328f, 0.1112808f, 0.2167454f, 0.2706822f,
    0.2167454f, 0.1112808f, 0.0366328f
};

__device__ __forceinline__ float clamp01(float v) {
    return fminf(fmaxf(v, 0.f), 1.f);
}

__global__ __launch_bounds__(256, 3)
void clarity_texture_kernel(const float* __restrict__ x,
                            const float* __restrict__ clar,
                            const float* __restrict__ tex,
                            float* __restrict__ out) {
    extern __shared__ float smem[];
    float* sLuma = smem;              // LH x SW
    float* sV31  = smem + LH * SW;    // OH x SW

    const int tid = threadIdx.x;
    const int x0  = blockIdx.x * OW;
    const int y0  = blockIdx.y * OH;
    const int b   = blockIdx.z;

    const float ca = tanhf(*clar) * 0.5f;
    const float ta = tanhf(*tex) * 0.3f;

    const size_t plane = (size_t)IMH * IMW;
    const float* xb = x + (size_t)b * 3 * plane;
    float* ob = out + (size_t)b * 3 * plane;

    // ---- Phase 1: luma tile with halo, vectorized float4 (zero-padded) ----
    // gx is always a multiple of 4 => each float4 is entirely in- or out-of-image.
    for (int i = tid; i < LH * (LW / 4); i += 256) {
        int row = i / (LW / 4);
        int cc  = i % (LW / 4);
        int gy  = y0 - 15 + row;
        int gx  = x0 - 16 + cc * 4;
        float4 l4 = make_float4(0.f, 0.f, 0.f, 0.f);
        if ((unsigned)gy < IMH && (unsigned)gx < IMW) {
            size_t idx = (size_t)gy * IMW + gx;
            float4 r4 = *(const float4*)&xb[idx];
            float4 g4 = *(const float4*)&xb[idx + plane];
            float4 b4 = *(const float4*)&xb[idx + 2 * plane];
            l4.x = 0.2126f * r4.x + 0.7152f * g4.x + 0.0722f * b4.x;
            l4.y = 0.2126f * r4.y + 0.7152f * g4.y + 0.0722f * b4.y;
            l4.z = 0.2126f * r4.z + 0.7152f * g4.z + 0.0722f * b4.z;
            l4.w = 0.2126f * r4.w + 0.7152f * g4.w + 0.0722f * b4.w;
        }
        *(float4*)&sLuma[row * SW + cc * 4] = l4;
    }
    __syncthreads();

    // ---- Phase 2: vertical 31-tap blur, 8 output rows per thread ----
    for (int s = tid; s < SW * (OH / 8); s += 256) {   // 160*4 = 640 items
        int col = s % SW;
        int r0  = (s / SW) * 8;
        float a[8] = {0.f, 0.f, 0.f, 0.f, 0.f, 0.f, 0.f, 0.f};
        #pragma unroll
        for (int k = 0; k < 38; k++) {
            float v = sLuma[(r0 + k) * SW + col];
            #pragma unroll
            for (int o = 0; o < 8; o++) {
                int j = k - o;
                if (j >= 0 && j < 31) a[o] += G31[j] * v;   // FFMA-imm
            }
        }
        #pragma unroll
        for (int o = 0; o < 8; o++)
            sV31[(r0 + o) * SW + col] = a[o];
    }
    __syncthreads();

    // ---- Phase 3: horizontal 31-tap + full 7-tap + combine, 8 cols/thread ----
    for (int s = tid; s < OH * (OW / 8); s += 256) {   // 32*16 = 512 items
        int strip = s % (OW / 8);
        int r     = s / (OW / 8);
        int c0    = strip * 8;

        // 31-tap horizontal over vertically blurred plane.
        // out(o) taps sV31 cols c0+1+o+k (k=0..30); chunks cover m = 0..39.
        float a31[8] = {0.f, 0.f, 0.f, 0.f, 0.f, 0.f, 0.f, 0.f};
        const float4* p31 = (const float4*)&sV31[r * SW + c0];
        #pragma unroll
        for (int chk = 0; chk < 10; chk++) {
            float4 v4 = p31[chk];
            float e[4] = {v4.x, v4.y, v4.z, v4.w};
            #pragma unroll
            for (int q = 0; q < 4; q++) {
                int m = chk * 4 + q;
                #pragma unroll
                for (int o = 0; o < 8; o++) {
                    int k = m - 1 - o;
                    if (k >= 0 && k < 31) a31[o] += G31[k] * e[q];
                }
            }
        }

        // 7-tap blur computed directly from sLuma (vertical then horizontal).
        // v7[m] = vertical 7-tap at sLuma col c0+13+m, m=0..13.
        float v7[14];
        #pragma unroll
        for (int m = 0; m < 14; m++) v7[m] = 0.f;
        #pragma unroll
        for (int rr = 0; rr < 7; rr++) {
            const float4* q4 = (const float4*)&sLuma[(r + 12 + rr) * SW + c0 + 12];
            #pragma unroll
            for (int chk = 0; chk < 4; chk++) {
                float4 v4 = q4[chk];
                float e[4] = {v4.x, v4.y, v4.z, v4.w};
                #pragma unroll
                for (int q = 0; q < 4; q++) {
                    int m = chk * 4 + q - 1;
                    if (m >= 0 && m < 14) v7[m] += G7[rr] * e[q];
                }
            }
        }
        float a7[8];
        #pragma unroll
        for (int o = 0; o < 8; o++) {
            float acc = 0.f;
            #pragma unroll
            for (int k = 0; k < 7; k++) acc += G7[k] * v7[o + k];
            a7[o] = acc;
        }

        // center luma for the 8 outputs
        float4 lA = *(const float4*)&sLuma[(r + 15) * SW + c0 + 16];
        float4 lB = *(const float4*)&sLuma[(r + 15) * SW + c0 + 20];
        float lum[8] = {lA.x, lA.y, lA.z, lA.w, lB.x, lB.y, lB.z, lB.w};

        float ratio[8];
        #pragma unroll
        for (int o = 0; o < 8; o++) {
            float le = lum[o] + ca * (lum[o] - a31[o]) + ta * (lum[o] - a7[o]);
            ratio[o] = __fdividef(le + 1e-6f, lum[o] + 1e-6f);
        }

        int gy = y0 + r;
        int gx = x0 + c0;
        size_t idx = (size_t)gy * IMW + gx;
        #pragma unroll
        for (int ch = 0; ch < 3; ch++) {
            size_t o0 = idx + (size_t)ch * plane;
            float4 xa = *(const float4*)&xb[o0];
            float4 xc = *(const float4*)&xb[o0 + 4];
            float4 ra, rc;
            ra.x = clamp01(xa.x * ratio[0]); ra.y = clamp01(xa.y * ratio[1]);
            ra.z = clamp01(xa.z * ratio[2]); ra.w = clamp01(xa.w * ratio[3]);
            rc.x = clamp01(xc.x * ratio[4]); rc.y = clamp01(xc.y * ratio[5]);
            rc.z = clamp01(xc.z * ratio[6]); rc.w = clamp01(xc.w * ratio[7]);
            *(float4*)&ob[o0]     = ra;
            *(float4*)&ob[o0 + 4] = rc;
        }
    }
}

extern "C" void kernel_launch(void* const* d_in, const int* in_sizes, int n_in,
                              void* d_out, int out_size) {
    const float* x    = (const float*)d_in[0];
    const float* clar = (const float*)d_in[1];
    const float* tex  = (const float*)d_in[2];
    float* out = (float*)d_out;

    cudaFuncSetAttribute(clarity_texture_kernel,
                         cudaFuncAttributeMaxDynamicSharedMemorySize, SMEM_BYTES);

    dim3 grid(IMW / OW, IMH / OH, NB);
    clarity_texture_kernel<<<grid, 256, SMEM_BYTES>>>(x, clar, tex, out);
}

// round 10
// speedup vs baseline: 1.4921x; 1.2596x over previous
#include <cuda_runtime.h>
#include <cuda_fp16.h>
#include <math.h>

#define IMW 1024
#define IMH 1024
#define NB  8
#define OW  128
#define OH  32
#define LW  160          // luma tile cols (halves): global x in [x0-16, x0+144)
#define LH  62           // luma tile rows: global y in [y0-15, y0+47)
#define SWH 160          // shared row stride in halves (320 bytes)
#define SMEM_BYTES ((LH + OH + OH) * SWH * 2)   // 126*320 = 40320 -> 4 CTAs/SM

// 31-tap gaussian (sigma=8), normalized, k=0..30 (center 15)
__device__ constexpr float G31[31] = {
    0.0090750f, 0.0113825f, 0.0140557f, 0.0170873f, 0.0204508f, 0.0240970f,
    0.0279530f, 0.0319233f, 0.0358923f, 0.0397292f, 0.0432944f, 0.0464481f,
    0.0490592f, 0.0510133f, 0.0522230f, 0.0526326f, 0.0522230f, 0.0510133f,
    0.0490592f, 0.0464481f, 0.0432944f, 0.0397292f, 0.0358923f, 0.0319233f,
    0.0279530f, 0.0240970f, 0.0204508f, 0.0170873f, 0.0140557f, 0.0113825f,
    0.0090750f
};
// 7-tap gaussian (sigma=1.5), normalized
__device__ constexpr float G7[7] = {
    0.0366328f, 0.1112808f, 0.2167454f, 0.2706822f,
    0.2167454f, 0.1112808f, 0.0366328f
};

__device__ __forceinline__ float clamp01(float v) {
    return fminf(fmaxf(v, 0.f), 1.f);
}

__global__ __launch_bounds__(256, 4)
void clarity_texture_kernel(const float* __restrict__ x,
                            const float* __restrict__ clar,
                            const float* __restrict__ tex,
                            float* __restrict__ out) {
    extern __shared__ __half smem[];
    __half* sLuma = smem;                 // LH x SWH
    __half* sV31  = smem + LH * SWH;      // OH x SWH  (vertical 31-tap)
    __half* sV7   = sV31 + OH * SWH;      // OH x SWH  (vertical 7-tap)

    const int tid = threadIdx.x;
    const int x0  = blockIdx.x * OW;
    const int y0  = blockIdx.y * OH;
    const int b   = blockIdx.z;

    const float ca = tanhf(*clar) * 0.5f;
    const float ta = tanhf(*tex) * 0.3f;

    const size_t plane = (size_t)IMH * IMW;
    const float* xb = x + (size_t)b * 3 * plane;
    float* ob = out + (size_t)b * 3 * plane;

    // ---- Phase 1: luma tile with halo (fp16 store), float4 global loads ----
    for (int i = tid; i < LH * (LW / 4); i += 256) {
        int row = i / (LW / 4);
        int cc  = i % (LW / 4);
        int gy  = y0 - 15 + row;
        int gx  = x0 - 16 + cc * 4;
        float4 l4 = make_float4(0.f, 0.f, 0.f, 0.f);
        if ((unsigned)gy < IMH && (unsigned)gx < IMW) {
            size_t idx = (size_t)gy * IMW + gx;
            float4 r4 = *(const float4*)&xb[idx];
            float4 g4 = *(const float4*)&xb[idx + plane];
            float4 b4 = *(const float4*)&xb[idx + 2 * plane];
            l4.x = 0.2126f * r4.x + 0.7152f * g4.x + 0.0722f * b4.x;
            l4.y = 0.2126f * r4.y + 0.7152f * g4.y + 0.0722f * b4.y;
            l4.z = 0.2126f * r4.z + 0.7152f * g4.z + 0.0722f * b4.z;
            l4.w = 0.2126f * r4.w + 0.7152f * g4.w + 0.0722f * b4.w;
        }
        __half* dst = &sLuma[row * SWH + cc * 4];
        *(__half2*)(dst)     = __floats2half2_rn(l4.x, l4.y);
        *(__half2*)(dst + 2) = __floats2half2_rn(l4.z, l4.w);
    }
    __syncthreads();

    // ---- Phase 2: vertical 31-tap AND 7-tap blurs.
    // Each thread: 2 adjacent columns (half2) x 4 output rows.
    for (int s = tid; s < (SWH / 2) * (OH / 4); s += 256) {   // 80*8 = 640
        int c  = s % (SWH / 2);
        int r0 = (s / (SWH / 2)) * 4;
        float2 a[4] = {{0.f,0.f},{0.f,0.f},{0.f,0.f},{0.f,0.f}};
        float2 w[4] = {{0.f,0.f},{0.f,0.f},{0.f,0.f},{0.f,0.f}};
        #pragma unroll
        for (int k = 0; k < 34; k++) {
            float2 v = __half22float2(*(const __half2*)&sLuma[(r0 + k) * SWH + 2 * c]);
            #pragma unroll
            for (int o = 0; o < 4; o++) {
                int i = k - o;
                if (i >= 0 && i < 31) {          // FFMA-imm weights
                    a[o].x += G31[i] * v.x;
                    a[o].y += G31[i] * v.y;
                }
                int j = k - 12 - o;              // 7-tap: luma rows r0+o+12 .. +18
                if (j >= 0 && j < 7) {
                    w[o].x += G7[j] * v.x;
                    w[o].y += G7[j] * v.y;
                }
            }
        }
        #pragma unroll
        for (int o = 0; o < 4; o++) {
            *(__half2*)&sV31[(r0 + o) * SWH + 2 * c] = __floats2half2_rn(a[o].x, a[o].y);
            *(__half2*)&sV7 [(r0 + o) * SWH + 2 * c] = __floats2half2_rn(w[o].x, w[o].y);
        }
    }
    __syncthreads();

    // ---- Phase 3: horizontal blurs + combine + clip, 8 output cols/thread ----
    for (int s = tid; s < OH * (OW / 8); s += 256) {   // 512 items
        int strip = s & 15;
        int r     = s >> 4;
        int c0    = strip * 8;

        // 31-tap horizontal: taps sV31 cols c0+1+o .. c0+31+o, window c0..c0+39.
        float a31[8] = {0.f,0.f,0.f,0.f,0.f,0.f,0.f,0.f};
        const uint4* p31 = (const uint4*)&sV31[r * SWH + c0];
        #pragma unroll
        for (int chk = 0; chk < 5; chk++) {
            uint4 u = p31[chk];
            float e[8];
            {
                float2 f;
                f = __half22float2(*(__half2*)&u.x); e[0]=f.x; e[1]=f.y;
                f = __half22float2(*(__half2*)&u.y); e[2]=f.x; e[3]=f.y;
                f = __half22float2(*(__half2*)&u.z); e[4]=f.x; e[5]=f.y;
                f = __half22float2(*(__half2*)&u.w); e[6]=f.x; e[7]=f.y;
            }
            #pragma unroll
            for (int m = 0; m < 8; m++) {
                int M = chk * 8 + m;
                #pragma unroll
                for (int o = 0; o < 8; o++) {
                    int k = M - 1 - o;
                    if (k >= 0 && k < 31) a31[o] += G31[k] * e[m];
                }
            }
        }

        // 7-tap horizontal over precomputed vertical 7-tap plane.
        // Taps sV7 cols c0+13+o+j (j=0..6); aligned window starts at c0+8.
        float e2[24];
        {
            const uint4* q4 = (const uint4*)&sV7[r * SWH + c0 + 8];
            #pragma unroll
            for (int chk = 0; chk < 3; chk++) {
                uint4 u = q4[chk];
                float2 f;
                f = __half22float2(*(__half2*)&u.x); e2[chk*8+0]=f.x; e2[chk*8+1]=f.y;
                f = __half22float2(*(__half2*)&u.y); e2[chk*8+2]=f.x; e2[chk*8+3]=f.y;
                f = __half22float2(*(__half2*)&u.z); e2[chk*8+4]=f.x; e2[chk*8+5]=f.y;
                f = __half22float2(*(__half2*)&u.w); e2[chk*8+6]=f.x; e2[chk*8+7]=f.y;
            }
        }
        float a7[8];
        #pragma unroll
        for (int o = 0; o < 8; o++) {
            float acc = 0.f;
            #pragma unroll
            for (int j = 0; j < 7; j++) acc += G7[j] * e2[5 + o + j];
            a7[o] = acc;
        }

        // center luma (8 halves, one LDS.128)
        float lum[8];
        {
            uint4 u = *(const uint4*)&sLuma[(r + 15) * SWH + c0 + 16];
            float2 f;
            f = __half22float2(*(__half2*)&u.x); lum[0]=f.x; lum[1]=f.y;
            f = __half22float2(*(__half2*)&u.y); lum[2]=f.x; lum[3]=f.y;
            f = __half22float2(*(__half2*)&u.z); lum[4]=f.x; lum[5]=f.y;
            f = __half22float2(*(__half2*)&u.w); lum[6]=f.x; lum[7]=f.y;
        }

        float ratio[8];
        #pragma unroll
        for (int o = 0; o < 8; o++) {
            float le = lum[o] + ca * (lum[o] - a31[o]) + ta * (lum[o] - a7[o]);
            ratio[o] = __fdividef(le + 1e-6f, lum[o] + 1e-6f);
        }

        int gy = y0 + r;
        int gx = x0 + c0;
        size_t idx = (size_t)gy * IMW + gx;
        #pragma unroll
        for (int ch = 0; ch < 3; ch++) {
            size_t o0 = idx + (size_t)ch * plane;
            float4 xa = *(const float4*)&xb[o0];
            float4 xc = *(const float4*)&xb[o0 + 4];
            float4 ra, rc;
            ra.x = clamp01(xa.x * ratio[0]); ra.y = clamp01(xa.y * ratio[1]);
            ra.z = clamp01(xa.z * ratio[2]); ra.w = clamp01(xa.w * ratio[3]);
            rc.x = clamp01(xc.x * ratio[4]); rc.y = clamp01(xc.y * ratio[5]);
            rc.z = clamp01(xc.z * ratio[6]); rc.w = clamp01(xc.w * ratio[7]);
            *(float4*)&ob[o0]     = ra;
            *(float4*)&ob[o0 + 4] = rc;
        }
    }
}

extern "C" void kernel_launch(void* const* d_in, const int* in_sizes, int n_in,
                              void* d_out, int out_size) {
    const float* x    = (const float*)d_in[0];
    const float* clar = (const float*)d_in[1];
    const float* tex  = (const float*)d_in[2];
    float* out = (float*)d_out;

    cudaFuncSetAttribute(clarity_texture_kernel,
                         cudaFuncAttributeMaxDynamicSharedMemorySize, SMEM_BYTES);

    dim3 grid(IMW / OW, IMH / OH, NB);
    clarity_texture_kernel<<<grid, 256, SMEM_BYTES>>>(x, clar, tex, out);
}